// round 11
// baseline (speedup 1.0000x reference)
#include <cuda_runtime.h>
#include <cuda_bf16.h>
#include <mma.h>

using namespace nvcuda;

#define N_NODES 512
#define HID     1024
#define MG      132          // rows of G = [Hx(128); Ip(4)]
#define MPAD    144          // padded for 48-row tiles
#define KD      4096
#define NE      16384
#define NOUT    513
#define NN      (N_NODES * N_NODES)
#define HPLEN   (N_NODES * HID)   // 524288
#define CH      16
#define CHLEN   (HPLEN / CH)      // 32768
#define RG      2
#define NRG     ((NOUT + RG - 1) / RG)   // 257

#define SPLITK  16
#define KLEN    (KD / SPLITK)     // 256
#define GM      48
#define GN      128
#define GK      32
#define NCH     (KLEN / GK)       // 8
#define SA_LD   40
#define SB_LD   136
#define GSPLIT_STRIDE (MPAD * HID)   // 147456
// smem (bf16 elems): A = 2buf*2part*48*40 = 7680 ; B = 2buf*2part*32*136 = 17408
#define SB_BASE 7680
#define GEMM_SMEM (7680 + 17408)          // 25088 elems
#define GEMM_SMEM_BYTES (GEMM_SMEM * 2)   // 50176

// ---------------- scratch (device globals; no allocation allowed) ----------
__device__ float          g_G[MG * HID];
__device__ float          g_Gsplit[SPLITK * GSPLIT_STRIDE];
__device__ float          g_gs1[MG];
__device__ float          g_gs2[MG];
__device__ int            g_winner[NN];
__device__ float          g_P[N_NODES * MG];
__device__ float          g_hp[HPLEN];
__device__ float          g_partial[NOUT * CH];
__device__ unsigned int   g_amax_bits;
__device__ __nv_bfloat16  g_Whi[KD * HID];
__device__ __nv_bfloat16  g_Wlo[KD * HID];
__device__ __nv_bfloat16  g_Ahi[MPAD * KD];
__device__ __nv_bfloat16  g_Alo[MPAD * KD];

__device__ __forceinline__ void split2(float x, __nv_bfloat16& h, __nv_bfloat16& l) {
    h = __float2bfloat16(x);
    l = __float2bfloat16(x - __bfloat162float(h));
}

__device__ __forceinline__ void cp16(void* dst, const void* src) {
    unsigned int d = (unsigned int)__cvta_generic_to_shared(dst);
    asm volatile("cp.async.cg.shared.global [%0], [%1], 16;\n" :: "r"(d), "l"(src));
}
__device__ __forceinline__ void cp_commit() {
    asm volatile("cp.async.commit_group;\n");
}
template <int N>
__device__ __forceinline__ void cp_wait() {
    asm volatile("cp.async.wait_group %0;\n" :: "n"(N));
}

#define NW4 (KD * HID / 4)        // 1048576 float4 total in W
#define NW4H (NW4 / 2)            // 524288 per half
#define NA4 (MPAD * KD / 4)       // 147456

// ---------------- K_prepW: W -> bf16 hi/lo, half at a time, 2 f4/thread ----
__global__ void __launch_bounds__(256) k_prepW(const float* __restrict__ W, int base4) {
    int id = base4 + (blockIdx.x * blockDim.x + threadIdx.x) * 2;
    #pragma unroll
    for (int u = 0; u < 2; u++) {
        int i = id + u;
        float4 w = *(const float4*)(W + (size_t)i * 4);
        __nv_bfloat16 h0, l0, h1, l1, h2, l2, h3, l3;
        split2(w.x, h0, l0); split2(w.y, h1, l1);
        split2(w.z, h2, l2); split2(w.w, h3, l3);
        __nv_bfloat162* dh = (__nv_bfloat162*)(g_Whi + (size_t)i * 4);
        __nv_bfloat162* dl = (__nv_bfloat162*)(g_Wlo + (size_t)i * 4);
        dh[0] = __nv_bfloat162(h0, h1); dh[1] = __nv_bfloat162(h2, h3);
        dl[0] = __nv_bfloat162(l0, l1); dl[1] = __nv_bfloat162(l2, l3);
    }
}

// ---------------- K_prepA: A(padded) -> bf16 hi/lo (edge stream) -----------
__global__ void __launch_bounds__(256) k_prepA(const float* __restrict__ X,
                                               const float* __restrict__ img) {
    int i = blockIdx.x * blockDim.x + threadIdx.x;
    int base = i * 4;
    int r = base >> 12;
    int j = base & 4095;
    float4 v;
    if (r < 128) {
        v = *(const float4*)(X + (size_t)r * KD + j);
    } else if (r < MG) {
        v = *(const float4*)(img + (r - 128) * 1024 + (j & 1023));
    } else {
        v = make_float4(0.f, 0.f, 0.f, 0.f);
    }
    __nv_bfloat16 h0, l0, h1, l1, h2, l2, h3, l3;
    split2(v.x, h0, l0); split2(v.y, h1, l1);
    split2(v.z, h2, l2); split2(v.w, h3, l3);
    __nv_bfloat162* dh = (__nv_bfloat162*)(g_Ahi + (size_t)base);
    __nv_bfloat162* dl = (__nv_bfloat162*)(g_Alo + (size_t)base);
    dh[0] = __nv_bfloat162(h0, h1); dh[1] = __nv_bfloat162(h2, h3);
    dl[0] = __nv_bfloat162(l0, l1); dl[1] = __nv_bfloat162(l2, l3);
}

// ---------------- K1: G_split = A @ W, GM=48 x GN=128, 4 warps -------------
#define SA_IDX(buf, part, row, col) ((((buf) * 2 + (part)) * GM + (row)) * SA_LD + (col))
#define SB_IDX(buf, part, row, col) (SB_BASE + (((buf) * 2 + (part)) * GK + (row)) * SB_LD + (col))

__global__ void __launch_bounds__(128, 4) k_gemm_bf16(int bz_base) {
    extern __shared__ __nv_bfloat16 smem[];

    int tid = threadIdx.x;
    int bx = blockIdx.x;      // N tile (8)
    int by = blockIdx.y;      // M tile (3)
    int bz = blockIdx.z + bz_base;   // K split (16 total)
    int m0 = by * GM;
    int n0 = bx * GN;
    int k0 = bz * KLEN;

    int wn = tid >> 5;        // 4 warps in N (32 cols each)

    wmma::fragment<wmma::accumulator, 16, 16, 16, float> acc[3][2];
    #pragma unroll
    for (int m = 0; m < 3; m++)
        #pragma unroll
        for (int n = 0; n < 2; n++)
            wmma::fill_fragment(acc[m][n], 0.f);

    auto load_chunk = [&](int buf, int kg) {
        // A: 2 parts x 48 rows x 4 float4 = 384 cp16; 3 per thread
        #pragma unroll
        for (int i = 0; i < 3; i++) {
            int idx = tid + 128 * i;
            int part = idx / 192;
            int j = idx % 192;
            int row = j >> 2;
            int col = (j & 3) << 3;
            const __nv_bfloat16* src =
                (part ? g_Alo : g_Ahi) + (size_t)(m0 + row) * KD + kg + col;
            cp16(&smem[SA_IDX(buf, part, row, col)], src);
        }
        // B: 2 parts x 32 rows x 16 float4 = 1024 cp16; 8 per thread
        #pragma unroll
        for (int i = 0; i < 8; i++) {
            int idx = tid + 128 * i;
            int part = idx >> 9;
            int j = idx & 511;
            int row = j >> 4;
            int col = (j & 15) << 3;
            const __nv_bfloat16* src =
                (part ? g_Wlo : g_Whi) + (size_t)(kg + row) * HID + n0 + col;
            cp16(&smem[SB_IDX(buf, part, row, col)], src);
        }
    };

    load_chunk(0, k0);
    cp_commit();

    for (int ch = 0; ch < NCH; ch++) {
        if (ch + 1 < NCH) {
            load_chunk((ch + 1) & 1, k0 + (ch + 1) * GK);
            cp_commit();
            cp_wait<1>();
        } else {
            cp_wait<0>();
        }
        __syncthreads();
        int buf = ch & 1;
        #pragma unroll
        for (int ks = 0; ks < GK; ks += 16) {
            wmma::fragment<wmma::matrix_a, 16, 16, 16, __nv_bfloat16, wmma::row_major> afh[3], afl[3];
            #pragma unroll
            for (int m = 0; m < 3; m++) {
                wmma::load_matrix_sync(afh[m], &smem[SA_IDX(buf, 0, m * 16, ks)], SA_LD);
                wmma::load_matrix_sync(afl[m], &smem[SA_IDX(buf, 1, m * 16, ks)], SA_LD);
            }
            #pragma unroll
            for (int n = 0; n < 2; n++) {
                wmma::fragment<wmma::matrix_b, 16, 16, 16, __nv_bfloat16, wmma::row_major> bfh, bfl;
                wmma::load_matrix_sync(bfh, &smem[SB_IDX(buf, 0, ks, wn * 32 + n * 16)], SB_LD);
                wmma::load_matrix_sync(bfl, &smem[SB_IDX(buf, 1, ks, wn * 32 + n * 16)], SB_LD);
                #pragma unroll
                for (int m = 0; m < 3; m++) {
                    wmma::mma_sync(acc[m][n], afh[m], bfh, acc[m][n]);
                    wmma::mma_sync(acc[m][n], afl[m], bfh, acc[m][n]);
                    wmma::mma_sync(acc[m][n], afh[m], bfl, acc[m][n]);
                }
            }
        }
        __syncthreads();
    }

    #pragma unroll
    for (int m = 0; m < 3; m++) {
        #pragma unroll
        for (int n = 0; n < 2; n++) {
            float* outp = g_Gsplit + (size_t)bz * GSPLIT_STRIDE
                        + (size_t)(m0 + m * 16) * HID + n0 + wn * 32 + n * 16;
            wmma::store_matrix_sync(outp, acc[m][n], HID, wmma::mem_row_major);
        }
    }
}

// ---------------- K2: split-K reduce + gs1/gs2 row dots --------------------
__global__ void __launch_bounds__(256) k_reduce_gs(const float* __restrict__ a) {
    int m = blockIdx.x;            // 0..131
    int t = threadIdx.x;           // 256
    float s1 = 0.f, s2 = 0.f;
    for (int c = t; c < HID; c += 256) {
        float s = 0.f;
        #pragma unroll
        for (int z = 0; z < SPLITK; z++)
            s += g_Gsplit[(size_t)z * GSPLIT_STRIDE + m * HID + c];
        g_G[m * HID + c] = s;
        s1 += s * a[c];
        s2 += s * a[HID + c];
    }
    __shared__ float sh1[256], sh2[256];
    sh1[t] = s1; sh2[t] = s2;
    __syncthreads();
    for (int s = 128; s > 0; s >>= 1) {
        if (t < s) { sh1[t] += sh1[t + s]; sh2[t] += sh2[t + s]; }
        __syncthreads();
    }
    if (t == 0) { g_gs1[m] = sh1[0]; g_gs2[m] = sh2[0]; }
}

// ---------------- K3: scatter winners (last edge wins) + amax --------------
__global__ void k_scatter(const int* __restrict__ er, const int* __restrict__ ec) {
    int e = blockIdx.x * blockDim.x + threadIdx.x;
    if (e < NE) atomicMax(&g_winner[er[e] * N_NODES + ec[e]], e);
}
__global__ void k_amax(const int* __restrict__ er, const int* __restrict__ ec,
                       const float* __restrict__ av) {
    int e = blockIdx.x * blockDim.x + threadIdx.x;
    if (e < NE && g_winner[er[e] * N_NODES + ec[e]] == e)
        atomicMax(&g_amax_bits, __float_as_uint(av[e]));   // av >= 0
}

// ---------------- K4: per-row softmax + new_adj + P ----------------
__global__ void __launch_bounds__(128) k_row(const float* __restrict__ adj_vals,
                                             float* __restrict__ out) {
    int r = blockIdx.x;
    int t = threadIdx.x;            // 128
    __shared__ float red[128];
    __shared__ float4 red4[128];

    float s1r = g_gs1[r & 127] + g_gs1[128 + (r >> 7)];

    float ev[4]; int w[4];
    float lmax = -1e30f;
    #pragma unroll
    for (int j = 0; j < 4; j++) {
        int c = t + 128 * j;
        float s2c = g_gs2[c & 127] + g_gs2[128 + j];
        int ww = g_winner[r * N_NODES + c];
        w[j] = ww;
        float x = 0.f;
        if (ww >= 0) { float v = s1r + s2c; x = v > 0.f ? v : 0.2f * v; }
        ev[j] = x;
        lmax = fmaxf(lmax, x);
    }
    red[t] = lmax; __syncthreads();
    for (int s = 64; s > 0; s >>= 1) {
        if (t < s) red[t] = fmaxf(red[t], red[t + s]);
        __syncthreads();
    }
    float rmax = red[0]; __syncthreads();

    float ex[4]; float lsum = 0.f;
    #pragma unroll
    for (int j = 0; j < 4; j++) { ex[j] = expf(ev[j] - rmax); lsum += ex[j]; }
    red[t] = lsum; __syncthreads();
    for (int s = 64; s > 0; s >>= 1) {
        if (t < s) red[t] += red[t + s];
        __syncthreads();
    }
    float inv = 1.f / red[0]; __syncthreads();

    float amax2 = 2.f * __uint_as_float(g_amax_bits);
    float invA = amax2 > 0.f ? 1.f / amax2 : 0.f;

    float attj[4]; float pm = 0.f;
    #pragma unroll
    for (int j = 0; j < 4; j++) {
        float att = ex[j] * inv;
        attj[j] = att;
        float adjn = (w[j] >= 0) ? (2.f * adj_vals[w[j]]) * invA : 0.f;
        out[r * N_NODES + t + 128 * j] = att * adjn;
        pm += att;
    }
    g_P[r * MG + t] = pm;          // c & 127 == t for all 4 cols

    // one float4 reduction for the 4 column-block sums
    red4[t] = make_float4(attj[0], attj[1], attj[2], attj[3]);
    __syncthreads();
    for (int s = 64; s > 0; s >>= 1) {
        if (t < s) {
            float4 a4 = red4[t], b4 = red4[t + s];
            red4[t] = make_float4(a4.x + b4.x, a4.y + b4.y, a4.z + b4.z, a4.w + b4.w);
        }
        __syncthreads();
    }
    if (t < 4) {
        float4 rr = red4[0];
        float v = (t == 0) ? rr.x : (t == 1) ? rr.y : (t == 2) ? rr.z : rr.w;
        g_P[r * MG + 128 + t] = v;
    }
}

// ---------------- K5: hp = P(512,132) @ G(132,1024) ----------------
__global__ void __launch_bounds__(256) k_hp() {
    __shared__ float Ps[32][MG];
    __shared__ float Gs[MG][32];
    int bx = blockIdx.x;            // col tile (32)
    int by = blockIdx.y;            // row tile (16)
    int tid = threadIdx.x;

    for (int i = tid; i < 32 * MG; i += 256) {
        int rr = i / MG, kk = i % MG;
        Ps[rr][kk] = g_P[(by * 32 + rr) * MG + kk];
    }
    for (int i = tid; i < MG * 32; i += 256) {
        int kk = i / 32, cc = i % 32;
        Gs[kk][cc] = g_G[kk * HID + bx * 32 + cc];
    }
    __syncthreads();

    int tx = tid & 7, ty = tid >> 3;   // ty: row 0..31, tx: col4 0..7
    float4 acc = make_float4(0.f, 0.f, 0.f, 0.f);
    #pragma unroll 4
    for (int k = 0; k < MG; k++) {
        float p = Ps[ty][k];
        float4 gv = *(float4*)&Gs[k][tx * 4];
        acc.x += p * gv.x; acc.y += p * gv.y;
        acc.z += p * gv.z; acc.w += p * gv.w;
    }
    int row = by * 32 + ty, col = bx * 32 + tx * 4;
    *(float4*)&g_hp[row * HID + col] = acc;
}

// ---------------- K6: gemv, RG=2 rows per block, CH=16 chunks (R7) ---------
__global__ void __launch_bounds__(256) k_gemv(const float* __restrict__ lin_w) {
    int chunk = blockIdx.x;          // 0..CH-1
    int rg = blockIdx.y;             // 0..NRG-1
    int t = threadIdx.x;             // 256
    int row0 = rg * RG;
    int r0 = row0 < NOUT ? row0 : NOUT - 1;
    int r1 = row0 + 1 < NOUT ? row0 + 1 : NOUT - 1;

    const float4* w0 = (const float4*)(lin_w + (size_t)r0 * HPLEN + (size_t)chunk * CHLEN);
    const float4* w1 = (const float4*)(lin_w + (size_t)r1 * HPLEN + (size_t)chunk * CHLEN);
    const float4* vp = (const float4*)(g_hp + (size_t)chunk * CHLEN);

    float a0 = 0.f, a1 = 0.f;
    #pragma unroll 8
    for (int i = t; i < CHLEN / 4; i += 256) {
        float4 v = __ldg(&vp[i]);
        float4 x = __ldcs(&w0[i]);
        float4 y = __ldcs(&w1[i]);
        a0 += x.x * v.x + x.y * v.y + x.z * v.z + x.w * v.w;
        a1 += y.x * v.x + y.y * v.y + y.z * v.z + y.w * v.w;
    }

    __shared__ float sh[2][256];
    sh[0][t] = a0; sh[1][t] = a1;
    __syncthreads();
    for (int s = 128; s > 0; s >>= 1) {
        if (t < s) { sh[0][t] += sh[0][t + s]; sh[1][t] += sh[1][t + s]; }
        __syncthreads();
    }
    if (t < RG) {
        int row = row0 + t;
        if (row < NOUT) g_partial[row * CH + chunk] = sh[t][0];
    }
}

// ---------------- K7: finalize + min/max normalize ----------------
__global__ void k_final(const float* __restrict__ lin_b, float* __restrict__ out) {
    __shared__ float vals[NOUT];
    __shared__ float smin[256], smax[256];
    int t = threadIdx.x;            // 256
    for (int i = t; i < NOUT; i += 256) {
        float s = lin_b[i];
        #pragma unroll
        for (int c = 0; c < CH; c++) s += g_partial[i * CH + c];
        vals[i] = s;
    }
    __syncthreads();
    float mn = 1e30f, mx = -1e30f;
    for (int i = t; i < NOUT; i += 256) {
        mn = fminf(mn, vals[i]);
        mx = fmaxf(mx, vals[i]);
    }
    smin[t] = mn; smax[t] = mx; __syncthreads();
    for (int s = 128; s > 0; s >>= 1) {
        if (t < s) {
            smin[t] = fminf(smin[t], smin[t + s]);
            smax[t] = fmaxf(smax[t], smax[t + s]);
        }
        __syncthreads();
    }
    float gmn = smin[0], gmx = smax[0];
    float denom = gmx - gmn;
    for (int i = t; i < NOUT; i += 256)
        out[NN + i] = (denom == 0.f) ? 0.5f : (vals[i] - gmn) / denom;
}

// ---------------- launch ----------------
extern "C" void kernel_launch(void* const* d_in, const int* in_sizes, int n_in,
                              void* d_out, int out_size) {
    const float* img = (const float*)d_in[0];
    const int*   er  = (const int*)d_in[1];
    const int*   ec  = (const int*)d_in[2];
    const float* av  = (const float*)d_in[3];
    const float* X   = (const float*)d_in[4];
    const float* W   = (const float*)d_in[5];
    const float* a   = (const float*)d_in[6];
    const float* lw  = (const float*)d_in[7];
    const float* lb  = (const float*)d_in[8];
    float* out = (float*)d_out;

    static cudaStream_t s2 = []() {
        cudaStream_t s; cudaStreamCreateWithFlags(&s, cudaStreamNonBlocking); return s;
    }();
    static cudaEvent_t e0 = []() {
        cudaEvent_t e; cudaEventCreateWithFlags(&e, cudaEventDisableTiming); return e;
    }();
    static cudaEvent_t e1 = []() {
        cudaEvent_t e; cudaEventCreateWithFlags(&e, cudaEventDisableTiming); return e;
    }();
    static cudaEvent_t eA = []() {
        cudaEvent_t e; cudaEventCreateWithFlags(&e, cudaEventDisableTiming); return e;
    }();
    static cudaEvent_t eW1 = []() {
        cudaEvent_t e; cudaEventCreateWithFlags(&e, cudaEventDisableTiming); return e;
    }();
    static bool attr_set = []() {
        cudaFuncSetAttribute(k_gemm_bf16, cudaFuncAttributeMaxDynamicSharedMemorySize,
                             GEMM_SMEM_BYTES);
        return true;
    }();
    (void)attr_set;

    void* winner_ptr = nullptr;
    void* amax_ptr = nullptr;
    cudaGetSymbolAddress(&winner_ptr, g_winner);
    cudaGetSymbolAddress(&amax_ptr, g_amax_bits);

    // fork to s2: A conversion, upper-half W conversion, then edge path
    cudaEventRecord(e0, 0);
    cudaStreamWaitEvent(s2, e0, 0);
    k_prepA<<<NA4 / 256, 256, 0, s2>>>(X, img);
    cudaEventRecord(eA, s2);
    k_prepW<<<NW4H / 512, 256, 0, s2>>>(W, NW4H);     // upper half (K rows 2048..4095)
    cudaEventRecord(eW1, s2);
    cudaMemsetAsync(winner_ptr, 0xFF, NN * sizeof(int), s2);        // winner = -1
    cudaMemsetAsync(amax_ptr, 0x00, sizeof(unsigned int), s2);      // amax = 0
    k_scatter<<<64, 256, 0, s2>>>(er, ec);
    k_amax<<<64, 256, 0, s2>>>(er, ec, av);
    cudaEventRecord(e1, s2);

    // main path: lower-half W conversion, then gemm halves pipelined
    k_prepW<<<NW4H / 512, 256>>>(W, 0);               // lower half (K rows 0..2047)
    cudaStreamWaitEvent(0, eA, 0);
    dim3 g1(8, 3, SPLITK / 2);
    k_gemm_bf16<<<g1, 128, GEMM_SMEM_BYTES>>>(0);     // bz 0..7  (needs W rows < 2048)
    cudaStreamWaitEvent(0, eW1, 0);
    k_gemm_bf16<<<g1, 128, GEMM_SMEM_BYTES>>>(8);     // bz 8..15 (needs W rows >= 2048)
    k_reduce_gs<<<MG, 256>>>(a);

    // join edge path
    cudaStreamWaitEvent(0, e1, 0);
    k_row<<<512, 128>>>(av, out);
    dim3 g5(32, 16);
    k_hp<<<g5, 256>>>();
    dim3 g6(CH, NRG);
    k_gemv<<<g6, 256>>>(lw);
    k_final<<<1, 256>>>(lb, out);
}

// round 12
// speedup vs baseline: 1.0447x; 1.0447x over previous
#include <cuda_runtime.h>
#include <cuda_bf16.h>
#include <mma.h>

using namespace nvcuda;

#define N_NODES 512
#define HID     1024
#define MG      132          // rows of G = [Hx(128); Ip(4)]
#define MPAD    144          // padded for 48-row tiles
#define KD      4096
#define NE      16384
#define NOUT    513
#define NN      (N_NODES * N_NODES)
#define HPLEN   (N_NODES * HID)   // 524288
#define CH      16
#define CHLEN   (HPLEN / CH)      // 32768
#define RG      2
#define NRG     ((NOUT + RG - 1) / RG)   // 257

#define SPLITK  16
#define KLEN    (KD / SPLITK)     // 256
#define GM      48
#define GN      128
#define GK      32
#define NCH     (KLEN / GK)       // 8
#define SA_LD   40
#define SB_LD   136
#define GSPLIT_STRIDE (MPAD * HID)   // 147456
// smem (bf16 elems): A = 2buf*2part*48*40 = 7680 ; B = 2buf*2part*32*136 = 17408
#define SB_BASE 7680
#define GEMM_SMEM (7680 + 17408)          // 25088 elems
#define GEMM_SMEM_BYTES (GEMM_SMEM * 2)   // 50176

// ---------------- scratch (device globals; no allocation allowed) ----------
__device__ float          g_G[MG * HID];
__device__ float          g_Gsplit[SPLITK * GSPLIT_STRIDE];
__device__ float          g_gs1[MG];
__device__ float          g_gs2[MG];
__device__ int            g_winner[NN];
__device__ float          g_P[N_NODES * MG];
__device__ float          g_hp[HPLEN];
__device__ float          g_partial[NOUT * CH];
__device__ unsigned int   g_amax_bits;
__device__ __nv_bfloat16  g_Whi[KD * HID];
__device__ __nv_bfloat16  g_Wlo[KD * HID];
__device__ __nv_bfloat16  g_Ahi[MPAD * KD];
__device__ __nv_bfloat16  g_Alo[MPAD * KD];

__device__ __forceinline__ void split2(float x, __nv_bfloat16& h, __nv_bfloat16& l) {
    h = __float2bfloat16(x);
    l = __float2bfloat16(x - __bfloat162float(h));
}

__device__ __forceinline__ void cp16(void* dst, const void* src) {
    unsigned int d = (unsigned int)__cvta_generic_to_shared(dst);
    asm volatile("cp.async.cg.shared.global [%0], [%1], 16;\n" :: "r"(d), "l"(src));
}
__device__ __forceinline__ void cp_commit() {
    asm volatile("cp.async.commit_group;\n");
}
template <int N>
__device__ __forceinline__ void cp_wait() {
    asm volatile("cp.async.wait_group %0;\n" :: "n"(N));
}

// ---------------- K_prep: W/A bf16 hi-lo conversion (R7 combined) ----------
#define NW4 (KD * HID / 4)        // 1048576
#define NA4 (MPAD * KD / 4)       // 147456
__global__ void __launch_bounds__(256) k_prep(const float* __restrict__ W,
                                              const float* __restrict__ X,
                                              const float* __restrict__ img) {
    int id = blockIdx.x * blockDim.x + threadIdx.x;
    if (id < NW4) {
        float4 w = *(const float4*)(W + (size_t)id * 4);
        __nv_bfloat16 h0, l0, h1, l1, h2, l2, h3, l3;
        split2(w.x, h0, l0); split2(w.y, h1, l1);
        split2(w.z, h2, l2); split2(w.w, h3, l3);
        __nv_bfloat162* dh = (__nv_bfloat162*)(g_Whi + (size_t)id * 4);
        __nv_bfloat162* dl = (__nv_bfloat162*)(g_Wlo + (size_t)id * 4);
        dh[0] = __nv_bfloat162(h0, h1); dh[1] = __nv_bfloat162(h2, h3);
        dl[0] = __nv_bfloat162(l0, l1); dl[1] = __nv_bfloat162(l2, l3);
    } else if (id < NW4 + NA4) {
        int i = id - NW4;
        int base = i * 4;
        int r = base >> 12;
        int j = base & 4095;
        float4 v;
        if (r < 128) {
            v = *(const float4*)(X + (size_t)r * KD + j);
        } else if (r < MG) {
            v = *(const float4*)(img + (r - 128) * 1024 + (j & 1023));
        } else {
            v = make_float4(0.f, 0.f, 0.f, 0.f);
        }
        __nv_bfloat16 h0, l0, h1, l1, h2, l2, h3, l3;
        split2(v.x, h0, l0); split2(v.y, h1, l1);
        split2(v.z, h2, l2); split2(v.w, h3, l3);
        __nv_bfloat162* dh = (__nv_bfloat162*)(g_Ahi + (size_t)base);
        __nv_bfloat162* dl = (__nv_bfloat162*)(g_Alo + (size_t)base);
        dh[0] = __nv_bfloat162(h0, h1); dh[1] = __nv_bfloat162(h2, h3);
        dl[0] = __nv_bfloat162(l0, l1); dl[1] = __nv_bfloat162(l2, l3);
    }
}

// ---------------- K1: G_split = A @ W, GM=48 x GN=128, 4 warps -------------
#define SA_IDX(buf, part, row, col) ((((buf) * 2 + (part)) * GM + (row)) * SA_LD + (col))
#define SB_IDX(buf, part, row, col) (SB_BASE + (((buf) * 2 + (part)) * GK + (row)) * SB_LD + (col))

__global__ void __launch_bounds__(128, 4) k_gemm_bf16() {
    extern __shared__ __nv_bfloat16 smem[];

    int tid = threadIdx.x;
    int bx = blockIdx.x;      // N tile (8)
    int by = blockIdx.y;      // M tile (3)
    int bz = blockIdx.z;      // K split (16)
    int m0 = by * GM;
    int n0 = bx * GN;
    int k0 = bz * KLEN;

    int wn = tid >> 5;        // 4 warps in N (32 cols each)

    wmma::fragment<wmma::accumulator, 16, 16, 16, float> acc[3][2];
    #pragma unroll
    for (int m = 0; m < 3; m++)
        #pragma unroll
        for (int n = 0; n < 2; n++)
            wmma::fill_fragment(acc[m][n], 0.f);

    auto load_chunk = [&](int buf, int kg) {
        // A: 2 parts x 48 rows x 4 float4 = 384 cp16; 3 per thread
        #pragma unroll
        for (int i = 0; i < 3; i++) {
            int idx = tid + 128 * i;
            int part = idx / 192;
            int j = idx % 192;
            int row = j >> 2;
            int col = (j & 3) << 3;
            const __nv_bfloat16* src =
                (part ? g_Alo : g_Ahi) + (size_t)(m0 + row) * KD + kg + col;
            cp16(&smem[SA_IDX(buf, part, row, col)], src);
        }
        // B: 2 parts x 32 rows x 16 float4 = 1024 cp16; 8 per thread
        #pragma unroll
        for (int i = 0; i < 8; i++) {
            int idx = tid + 128 * i;
            int part = idx >> 9;
            int j = idx & 511;
            int row = j >> 4;
            int col = (j & 15) << 3;
            const __nv_bfloat16* src =
                (part ? g_Wlo : g_Whi) + (size_t)(kg + row) * HID + n0 + col;
            cp16(&smem[SB_IDX(buf, part, row, col)], src);
        }
    };

    load_chunk(0, k0);
    cp_commit();

    for (int ch = 0; ch < NCH; ch++) {
        if (ch + 1 < NCH) {
            load_chunk((ch + 1) & 1, k0 + (ch + 1) * GK);
            cp_commit();
            cp_wait<1>();
        } else {
            cp_wait<0>();
        }
        __syncthreads();
        int buf = ch & 1;
        #pragma unroll
        for (int ks = 0; ks < GK; ks += 16) {
            wmma::fragment<wmma::matrix_a, 16, 16, 16, __nv_bfloat16, wmma::row_major> afh[3], afl[3];
            #pragma unroll
            for (int m = 0; m < 3; m++) {
                wmma::load_matrix_sync(afh[m], &smem[SA_IDX(buf, 0, m * 16, ks)], SA_LD);
                wmma::load_matrix_sync(afl[m], &smem[SA_IDX(buf, 1, m * 16, ks)], SA_LD);
            }
            #pragma unroll
            for (int n = 0; n < 2; n++) {
                wmma::fragment<wmma::matrix_b, 16, 16, 16, __nv_bfloat16, wmma::row_major> bfh, bfl;
                wmma::load_matrix_sync(bfh, &smem[SB_IDX(buf, 0, ks, wn * 32 + n * 16)], SB_LD);
                wmma::load_matrix_sync(bfl, &smem[SB_IDX(buf, 1, ks, wn * 32 + n * 16)], SB_LD);
                #pragma unroll
                for (int m = 0; m < 3; m++) {
                    wmma::mma_sync(acc[m][n], afh[m], bfh, acc[m][n]);
                    wmma::mma_sync(acc[m][n], afl[m], bfh, acc[m][n]);
                    wmma::mma_sync(acc[m][n], afh[m], bfl, acc[m][n]);
                }
            }
        }
        __syncthreads();
    }

    #pragma unroll
    for (int m = 0; m < 3; m++) {
        #pragma unroll
        for (int n = 0; n < 2; n++) {
            float* outp = g_Gsplit + (size_t)bz * GSPLIT_STRIDE
                        + (size_t)(m0 + m * 16) * HID + n0 + wn * 32 + n * 16;
            wmma::store_matrix_sync(outp, acc[m][n], HID, wmma::mem_row_major);
        }
    }
}

// ---------------- K2: split-K reduce + gs1/gs2 row dots --------------------
__global__ void __launch_bounds__(256) k_reduce_gs(const float* __restrict__ a) {
    int m = blockIdx.x;            // 0..131
    int t = threadIdx.x;           // 256
    float s1 = 0.f, s2 = 0.f;
    for (int c = t; c < HID; c += 256) {
        float s = 0.f;
        #pragma unroll
        for (int z = 0; z < SPLITK; z++)
            s += g_Gsplit[(size_t)z * GSPLIT_STRIDE + m * HID + c];
        g_G[m * HID + c] = s;
        s1 += s * a[c];
        s2 += s * a[HID + c];
    }
    __shared__ float sh1[256], sh2[256];
    sh1[t] = s1; sh2[t] = s2;
    __syncthreads();
    for (int s = 128; s > 0; s >>= 1) {
        if (t < s) { sh1[t] += sh1[t + s]; sh2[t] += sh2[t + s]; }
        __syncthreads();
    }
    if (t == 0) { g_gs1[m] = sh1[0]; g_gs2[m] = sh2[0]; }
}

// ---------------- K3: scatter winners (last edge wins) + amax --------------
__global__ void k_scatter(const int* __restrict__ er, const int* __restrict__ ec) {
    int e = blockIdx.x * blockDim.x + threadIdx.x;
    if (e < NE) atomicMax(&g_winner[er[e] * N_NODES + ec[e]], e);
}
__global__ void k_amax(const int* __restrict__ er, const int* __restrict__ ec,
                       const float* __restrict__ av) {
    int e = blockIdx.x * blockDim.x + threadIdx.x;
    if (e < NE && g_winner[er[e] * N_NODES + ec[e]] == e)
        atomicMax(&g_amax_bits, __float_as_uint(av[e]));   // av >= 0
}

// ---------------- K4: per-row softmax + new_adj + P ----------------
__global__ void __launch_bounds__(128) k_row(const float* __restrict__ adj_vals,
                                             float* __restrict__ out) {
    int r = blockIdx.x;
    int t = threadIdx.x;            // 128
    __shared__ float red[128];
    __shared__ float4 red4[128];

    float s1r = g_gs1[r & 127] + g_gs1[128 + (r >> 7)];

    float ev[4]; int w[4];
    float lmax = -1e30f;
    #pragma unroll
    for (int j = 0; j < 4; j++) {
        int c = t + 128 * j;
        float s2c = g_gs2[c & 127] + g_gs2[128 + j];
        int ww = g_winner[r * N_NODES + c];
        w[j] = ww;
        float x = 0.f;
        if (ww >= 0) { float v = s1r + s2c; x = v > 0.f ? v : 0.2f * v; }
        ev[j] = x;
        lmax = fmaxf(lmax, x);
    }
    red[t] = lmax; __syncthreads();
    for (int s = 64; s > 0; s >>= 1) {
        if (t < s) red[t] = fmaxf(red[t], red[t + s]);
        __syncthreads();
    }
    float rmax = red[0]; __syncthreads();

    float ex[4]; float lsum = 0.f;
    #pragma unroll
    for (int j = 0; j < 4; j++) { ex[j] = expf(ev[j] - rmax); lsum += ex[j]; }
    red[t] = lsum; __syncthreads();
    for (int s = 64; s > 0; s >>= 1) {
        if (t < s) red[t] += red[t + s];
        __syncthreads();
    }
    float inv = 1.f / red[0]; __syncthreads();

    float amax2 = 2.f * __uint_as_float(g_amax_bits);
    float invA = amax2 > 0.f ? 1.f / amax2 : 0.f;

    float attj[4]; float pm = 0.f;
    #pragma unroll
    for (int j = 0; j < 4; j++) {
        float att = ex[j] * inv;
        attj[j] = att;
        float adjn = (w[j] >= 0) ? (2.f * adj_vals[w[j]]) * invA : 0.f;
        out[r * N_NODES + t + 128 * j] = att * adjn;
        pm += att;
    }
    g_P[r * MG + t] = pm;          // c & 127 == t for all 4 cols

    // one float4 reduction for the 4 column-block sums
    red4[t] = make_float4(attj[0], attj[1], attj[2], attj[3]);
    __syncthreads();
    for (int s = 64; s > 0; s >>= 1) {
        if (t < s) {
            float4 a4 = red4[t], b4 = red4[t + s];
            red4[t] = make_float4(a4.x + b4.x, a4.y + b4.y, a4.z + b4.z, a4.w + b4.w);
        }
        __syncthreads();
    }
    if (t < 4) {
        float4 rr = red4[0];
        float v = (t == 0) ? rr.x : (t == 1) ? rr.y : (t == 2) ? rr.z : rr.w;
        g_P[r * MG + 128 + t] = v;
    }
}

// ---------------- K5: hp = P(512,132) @ G(132,1024) ----------------
__global__ void __launch_bounds__(256) k_hp() {
    __shared__ float Ps[32][MG];
    __shared__ float Gs[MG][32];
    int bx = blockIdx.x;            // col tile (32)
    int by = blockIdx.y;            // row tile (16)
    int tid = threadIdx.x;

    for (int i = tid; i < 32 * MG; i += 256) {
        int rr = i / MG, kk = i % MG;
        Ps[rr][kk] = g_P[(by * 32 + rr) * MG + kk];
    }
    for (int i = tid; i < MG * 32; i += 256) {
        int kk = i / 32, cc = i % 32;
        Gs[kk][cc] = g_G[kk * HID + bx * 32 + cc];
    }
    __syncthreads();

    int tx = tid & 7, ty = tid >> 3;   // ty: row 0..31, tx: col4 0..7
    float4 acc = make_float4(0.f, 0.f, 0.f, 0.f);
    #pragma unroll 4
    for (int k = 0; k < MG; k++) {
        float p = Ps[ty][k];
        float4 gv = *(float4*)&Gs[k][tx * 4];
        acc.x += p * gv.x; acc.y += p * gv.y;
        acc.z += p * gv.z; acc.w += p * gv.w;
    }
    int row = by * 32 + ty, col = bx * 32 + tx * 4;
    *(float4*)&g_hp[row * HID + col] = acc;
}

// ---------------- K6: gemv, RG=2 rows per block, CH=16 chunks (R7) ---------
__global__ void __launch_bounds__(256) k_gemv(const float* __restrict__ lin_w) {
    int chunk = blockIdx.x;          // 0..CH-1
    int rg = blockIdx.y;             // 0..NRG-1
    int t = threadIdx.x;             // 256
    int row0 = rg * RG;
    int r0 = row0 < NOUT ? row0 : NOUT - 1;
    int r1 = row0 + 1 < NOUT ? row0 + 1 : NOUT - 1;

    const float4* w0 = (const float4*)(lin_w + (size_t)r0 * HPLEN + (size_t)chunk * CHLEN);
    const float4* w1 = (const float4*)(lin_w + (size_t)r1 * HPLEN + (size_t)chunk * CHLEN);
    const float4* vp = (const float4*)(g_hp + (size_t)chunk * CHLEN);

    float a0 = 0.f, a1 = 0.f;
    #pragma unroll 8
    for (int i = t; i < CHLEN / 4; i += 256) {
        float4 v = __ldg(&vp[i]);
        float4 x = __ldcs(&w0[i]);
        float4 y = __ldcs(&w1[i]);
        a0 += x.x * v.x + x.y * v.y + x.z * v.z + x.w * v.w;
        a1 += y.x * v.x + y.y * v.y + y.z * v.z + y.w * v.w;
    }

    __shared__ float sh[2][256];
    sh[0][t] = a0; sh[1][t] = a1;
    __syncthreads();
    for (int s = 128; s > 0; s >>= 1) {
        if (t < s) { sh[0][t] += sh[0][t + s]; sh[1][t] += sh[1][t + s]; }
        __syncthreads();
    }
    if (t < RG) {
        int row = row0 + t;
        if (row < NOUT) g_partial[row * CH + chunk] = sh[t][0];
    }
}

// ---------------- K7: finalize + min/max normalize ----------------
__global__ void k_final(const float* __restrict__ lin_b, float* __restrict__ out) {
    __shared__ float vals[NOUT];
    __shared__ float smin[256], smax[256];
    int t = threadIdx.x;            // 256
    for (int i = t; i < NOUT; i += 256) {
        float s = lin_b[i];
        #pragma unroll
        for (int c = 0; c < CH; c++) s += g_partial[i * CH + c];
        vals[i] = s;
    }
    __syncthreads();
    float mn = 1e30f, mx = -1e30f;
    for (int i = t; i < NOUT; i += 256) {
        mn = fminf(mn, vals[i]);
        mx = fmaxf(mx, vals[i]);
    }
    smin[t] = mn; smax[t] = mx; __syncthreads();
    for (int s = 128; s > 0; s >>= 1) {
        if (t < s) {
            smin[t] = fminf(smin[t], smin[t + s]);
            smax[t] = fmaxf(smax[t], smax[t + s]);
        }
        __syncthreads();
    }
    float gmn = smin[0], gmx = smax[0];
    float denom = gmx - gmn;
    for (int i = t; i < NOUT; i += 256)
        out[NN + i] = (denom == 0.f) ? 0.5f : (vals[i] - gmn) / denom;
}

// ---------------- launch (exact R7 structure) ----------------
extern "C" void kernel_launch(void* const* d_in, const int* in_sizes, int n_in,
                              void* d_out, int out_size) {
    const float* img = (const float*)d_in[0];
    const int*   er  = (const int*)d_in[1];
    const int*   ec  = (const int*)d_in[2];
    const float* av  = (const float*)d_in[3];
    const float* X   = (const float*)d_in[4];
    const float* W   = (const float*)d_in[5];
    const float* a   = (const float*)d_in[6];
    const float* lw  = (const float*)d_in[7];
    const float* lb  = (const float*)d_in[8];
    float* out = (float*)d_out;

    static cudaStream_t s2 = []() {
        cudaStream_t s; cudaStreamCreateWithFlags(&s, cudaStreamNonBlocking); return s;
    }();
    static cudaEvent_t e0 = []() {
        cudaEvent_t e; cudaEventCreateWithFlags(&e, cudaEventDisableTiming); return e;
    }();
    static cudaEvent_t e1 = []() {
        cudaEvent_t e; cudaEventCreateWithFlags(&e, cudaEventDisableTiming); return e;
    }();
    static bool attr_set = []() {
        cudaFuncSetAttribute(k_gemm_bf16, cudaFuncAttributeMaxDynamicSharedMemorySize,
                             GEMM_SMEM_BYTES);
        return true;
    }();
    (void)attr_set;

    void* winner_ptr = nullptr;
    void* amax_ptr = nullptr;
    cudaGetSymbolAddress(&winner_ptr, g_winner);
    cudaGetSymbolAddress(&amax_ptr, g_amax_bits);

    // fork: edge path on s2
    cudaEventRecord(e0, 0);
    cudaStreamWaitEvent(s2, e0, 0);
    cudaMemsetAsync(winner_ptr, 0xFF, NN * sizeof(int), s2);        // winner = -1
    cudaMemsetAsync(amax_ptr, 0x00, sizeof(unsigned int), s2);      // amax = 0
    k_scatter<<<64, 256, 0, s2>>>(er, ec);
    k_amax<<<64, 256, 0, s2>>>(er, ec, av);
    cudaEventRecord(e1, s2);

    // main path on default stream
    int prep_blocks = (NW4 + NA4 + 255) / 256;
    k_prep<<<prep_blocks, 256>>>(W, X, img);
    dim3 g1(8, 3, SPLITK);
    k_gemm_bf16<<<g1, 128, GEMM_SMEM_BYTES>>>();
    k_reduce_gs<<<MG, 256>>>(a);

    // join
    cudaStreamWaitEvent(0, e1, 0);
    k_row<<<512, 128>>>(av, out);
    dim3 g5(32, 16);
    k_hp<<<g5, 256>>>();
    dim3 g6(CH, NRG);
    k_gemv<<<g6, 256>>>(lw);
    k_final<<<1, 256>>>(lb, out);
}

// round 13
// speedup vs baseline: 1.0541x; 1.0089x over previous
#include <cuda_runtime.h>
#include <cuda_bf16.h>
#include <mma.h>

using namespace nvcuda;

#define N_NODES 512
#define HID     1024
#define MG      132          // rows of G = [Hx(128); Ip(4)]
#define MPAD    144          // padded for 48-row tiles
#define KD      4096
#define NE      16384
#define NOUT    513
#define NN      (N_NODES * N_NODES)
#define HPLEN   (N_NODES * HID)   // 524288
#define CH      16
#define CHLEN   (HPLEN / CH)      // 32768
#define RG      2
#define NRG     ((NOUT + RG - 1) / RG)   // 257

#define SPLITK  16
#define KLEN    (KD / SPLITK)     // 256
#define GM      48
#define GN      128
#define GK      32
#define NCH     (KLEN / GK)       // 8
#define SA_LD   40
#define SB_LD   136
#define GSPLIT_STRIDE (MPAD * HID)   // 147456
// smem (bf16 elems): A = 2buf*2part*48*40 = 7680 ; B = 2buf*2part*32*136 = 17408
#define SB_BASE 7680
#define GEMM_SMEM (7680 + 17408)          // 25088 elems
#define GEMM_SMEM_BYTES (GEMM_SMEM * 2)   // 50176

// ---------------- scratch (device globals; no allocation allowed) ----------
__device__ float          g_G[MG * HID];
__device__ float          g_Gsplit[SPLITK * GSPLIT_STRIDE];
__device__ float          g_gs1[MG];
__device__ float          g_gs2[MG];
__device__ int            g_winner[NN];
__device__ float          g_P[N_NODES * MG];
__device__ float          g_hp[HPLEN];
__device__ float          g_partial[NOUT * CH];
__device__ unsigned int   g_amax_bits;
__device__ __nv_bfloat16  g_Whi[KD * HID];
__device__ __nv_bfloat16  g_Wlo[KD * HID];
__device__ __nv_bfloat16  g_Ahi[MPAD * KD];
__device__ __nv_bfloat16  g_Alo[MPAD * KD];

__device__ __forceinline__ void split2(float x, __nv_bfloat16& h, __nv_bfloat16& l) {
    h = __float2bfloat16(x);
    l = __float2bfloat16(x - __bfloat162float(h));
}

__device__ __forceinline__ unsigned int pack2(__nv_bfloat16 a, __nv_bfloat16 b) {
    __nv_bfloat162 t(a, b);
    return *(unsigned int*)&t;
}

// convert 8 floats (two float4) -> one uint4 hi + one uint4 lo
__device__ __forceinline__ void conv8(float4 v0, float4 v1, uint4& hi, uint4& lo) {
    __nv_bfloat16 h[8], l[8];
    split2(v0.x, h[0], l[0]); split2(v0.y, h[1], l[1]);
    split2(v0.z, h[2], l[2]); split2(v0.w, h[3], l[3]);
    split2(v1.x, h[4], l[4]); split2(v1.y, h[5], l[5]);
    split2(v1.z, h[6], l[6]); split2(v1.w, h[7], l[7]);
    hi = make_uint4(pack2(h[0], h[1]), pack2(h[2], h[3]), pack2(h[4], h[5]), pack2(h[6], h[7]));
    lo = make_uint4(pack2(l[0], l[1]), pack2(l[2], l[3]), pack2(l[4], l[5]), pack2(l[6], l[7]));
}

__device__ __forceinline__ void cp16(void* dst, const void* src) {
    unsigned int d = (unsigned int)__cvta_generic_to_shared(dst);
    asm volatile("cp.async.cg.shared.global [%0], [%1], 16;\n" :: "r"(d), "l"(src));
}
__device__ __forceinline__ void cp_commit() {
    asm volatile("cp.async.commit_group;\n");
}
template <int N>
__device__ __forceinline__ void cp_wait() {
    asm volatile("cp.async.wait_group %0;\n" :: "n"(N));
}

// ---------------- K_prep: W/A bf16 hi-lo conversion, 8 floats/thread -------
#define NW4 (KD * HID / 4)        // 1048576 float4 in W
#define NA4 (MPAD * KD / 4)       // 147456 float4 in padded A
#define NW8 (NW4 / 2)             // 524288 8-float groups
#define NA8 (NA4 / 2)             // 73728
__global__ void __launch_bounds__(256) k_prep(const float* __restrict__ W,
                                              const float* __restrict__ X,
                                              const float* __restrict__ img) {
    int id = blockIdx.x * blockDim.x + threadIdx.x;
    if (id < NW8) {
        size_t base = (size_t)id * 8;
        float4 v0 = *(const float4*)(W + base);
        float4 v1 = *(const float4*)(W + base + 4);
        uint4 hi, lo;
        conv8(v0, v1, hi, lo);
        *(uint4*)(g_Whi + base) = hi;
        *(uint4*)(g_Wlo + base) = lo;
    } else if (id < NW8 + NA8) {
        int i = id - NW8;
        size_t base = (size_t)i * 8;
        int r = (int)(base >> 12);
        int j = (int)(base & 4095);
        float4 v0, v1;
        if (r < 128) {
            v0 = *(const float4*)(X + (size_t)r * KD + j);
            v1 = *(const float4*)(X + (size_t)r * KD + j + 4);
        } else if (r < MG) {
            const float* ip = img + (r - 128) * 1024 + (j & 1023);
            v0 = *(const float4*)(ip);
            v1 = *(const float4*)(ip + 4);
        } else {
            v0 = make_float4(0.f, 0.f, 0.f, 0.f);
            v1 = v0;
        }
        uint4 hi, lo;
        conv8(v0, v1, hi, lo);
        *(uint4*)(g_Ahi + base) = hi;
        *(uint4*)(g_Alo + base) = lo;
    }
}

// ---------------- K1: G_split = A @ W, GM=48 x GN=128, 4 warps -------------
#define SA_IDX(buf, part, row, col) ((((buf) * 2 + (part)) * GM + (row)) * SA_LD + (col))
#define SB_IDX(buf, part, row, col) (SB_BASE + (((buf) * 2 + (part)) * GK + (row)) * SB_LD + (col))

__global__ void __launch_bounds__(128, 4) k_gemm_bf16() {
    extern __shared__ __nv_bfloat16 smem[];

    int tid = threadIdx.x;
    int bx = blockIdx.x;      // N tile (8)
    int by = blockIdx.y;      // M tile (3)
    int bz = blockIdx.z;      // K split (16)
    int m0 = by * GM;
    int n0 = bx * GN;
    int k0 = bz * KLEN;

    int wn = tid >> 5;        // 4 warps in N (32 cols each)

    wmma::fragment<wmma::accumulator, 16, 16, 16, float> acc[3][2];
    #pragma unroll
    for (int m = 0; m < 3; m++)
        #pragma unroll
        for (int n = 0; n < 2; n++)
            wmma::fill_fragment(acc[m][n], 0.f);

    auto load_chunk = [&](int buf, int kg) {
        // A: 2 parts x 48 rows x 4 float4 = 384 cp16; 3 per thread
        #pragma unroll
        for (int i = 0; i < 3; i++) {
            int idx = tid + 128 * i;
            int part = idx / 192;
            int j = idx % 192;
            int row = j >> 2;
            int col = (j & 3) << 3;
            const __nv_bfloat16* src =
                (part ? g_Alo : g_Ahi) + (size_t)(m0 + row) * KD + kg + col;
            cp16(&smem[SA_IDX(buf, part, row, col)], src);
        }
        // B: 2 parts x 32 rows x 16 float4 = 1024 cp16; 8 per thread
        #pragma unroll
        for (int i = 0; i < 8; i++) {
            int idx = tid + 128 * i;
            int part = idx >> 9;
            int j = idx & 511;
            int row = j >> 4;
            int col = (j & 15) << 3;
            const __nv_bfloat16* src =
                (part ? g_Wlo : g_Whi) + (size_t)(kg + row) * HID + n0 + col;
            cp16(&smem[SB_IDX(buf, part, row, col)], src);
        }
    };

    load_chunk(0, k0);
    cp_commit();

    for (int ch = 0; ch < NCH; ch++) {
        if (ch + 1 < NCH) {
            load_chunk((ch + 1) & 1, k0 + (ch + 1) * GK);
            cp_commit();
            cp_wait<1>();
        } else {
            cp_wait<0>();
        }
        __syncthreads();
        int buf = ch & 1;
        #pragma unroll
        for (int ks = 0; ks < GK; ks += 16) {
            wmma::fragment<wmma::matrix_a, 16, 16, 16, __nv_bfloat16, wmma::row_major> afh[3], afl[3];
            #pragma unroll
            for (int m = 0; m < 3; m++) {
                wmma::load_matrix_sync(afh[m], &smem[SA_IDX(buf, 0, m * 16, ks)], SA_LD);
                wmma::load_matrix_sync(afl[m], &smem[SA_IDX(buf, 1, m * 16, ks)], SA_LD);
            }
            #pragma unroll
            for (int n = 0; n < 2; n++) {
                wmma::fragment<wmma::matrix_b, 16, 16, 16, __nv_bfloat16, wmma::row_major> bfh, bfl;
                wmma::load_matrix_sync(bfh, &smem[SB_IDX(buf, 0, ks, wn * 32 + n * 16)], SB_LD);
                wmma::load_matrix_sync(bfl, &smem[SB_IDX(buf, 1, ks, wn * 32 + n * 16)], SB_LD);
                #pragma unroll
                for (int m = 0; m < 3; m++) {
                    wmma::mma_sync(acc[m][n], afh[m], bfh, acc[m][n]);
                    wmma::mma_sync(acc[m][n], afl[m], bfh, acc[m][n]);
                    wmma::mma_sync(acc[m][n], afh[m], bfl, acc[m][n]);
                }
            }
        }
        __syncthreads();
    }

    #pragma unroll
    for (int m = 0; m < 3; m++) {
        #pragma unroll
        for (int n = 0; n < 2; n++) {
            float* outp = g_Gsplit + (size_t)bz * GSPLIT_STRIDE
                        + (size_t)(m0 + m * 16) * HID + n0 + wn * 32 + n * 16;
            wmma::store_matrix_sync(outp, acc[m][n], HID, wmma::mem_row_major);
        }
    }
}

// ---------------- K2: split-K reduce + gs1/gs2 row dots --------------------
__global__ void __launch_bounds__(256) k_reduce_gs(const float* __restrict__ a) {
    int m = blockIdx.x;            // 0..131
    int t = threadIdx.x;           // 256
    float s1 = 0.f, s2 = 0.f;
    for (int c = t; c < HID; c += 256) {
        float s = 0.f;
        #pragma unroll
        for (int z = 0; z < SPLITK; z++)
            s += g_Gsplit[(size_t)z * GSPLIT_STRIDE + m * HID + c];
        g_G[m * HID + c] = s;
        s1 += s * a[c];
        s2 += s * a[HID + c];
    }
    __shared__ float sh1[256], sh2[256];
    sh1[t] = s1; sh2[t] = s2;
    __syncthreads();
    for (int s = 128; s > 0; s >>= 1) {
        if (t < s) { sh1[t] += sh1[t + s]; sh2[t] += sh2[t + s]; }
        __syncthreads();
    }
    if (t == 0) { g_gs1[m] = sh1[0]; g_gs2[m] = sh2[0]; }
}

// ---------------- K3: scatter winners (last edge wins) + amax --------------
__global__ void k_scatter(const int* __restrict__ er, const int* __restrict__ ec) {
    int e = blockIdx.x * blockDim.x + threadIdx.x;
    if (e < NE) atomicMax(&g_winner[er[e] * N_NODES + ec[e]], e);
}
__global__ void k_amax(const int* __restrict__ er, const int* __restrict__ ec,
                       const float* __restrict__ av) {
    int e = blockIdx.x * blockDim.x + threadIdx.x;
    if (e < NE && g_winner[er[e] * N_NODES + ec[e]] == e)
        atomicMax(&g_amax_bits, __float_as_uint(av[e]));   // av >= 0
}

// ---------------- K4: per-row softmax + new_adj + P ----------------
__global__ void __launch_bounds__(128) k_row(const float* __restrict__ adj_vals,
                                             float* __restrict__ out) {
    int r = blockIdx.x;
    int t = threadIdx.x;            // 128
    __shared__ float red[128];
    __shared__ float4 red4[128];

    float s1r = g_gs1[r & 127] + g_gs1[128 + (r >> 7)];

    float ev[4]; int w[4];
    float lmax = -1e30f;
    #pragma unroll
    for (int j = 0; j < 4; j++) {
        int c = t + 128 * j;
        float s2c = g_gs2[c & 127] + g_gs2[128 + j];
        int ww = g_winner[r * N_NODES + c];
        w[j] = ww;
        float x = 0.f;
        if (ww >= 0) { float v = s1r + s2c; x = v > 0.f ? v : 0.2f * v; }
        ev[j] = x;
        lmax = fmaxf(lmax, x);
    }
    red[t] = lmax; __syncthreads();
    for (int s = 64; s > 0; s >>= 1) {
        if (t < s) red[t] = fmaxf(red[t], red[t + s]);
        __syncthreads();
    }
    float rmax = red[0]; __syncthreads();

    float ex[4]; float lsum = 0.f;
    #pragma unroll
    for (int j = 0; j < 4; j++) { ex[j] = expf(ev[j] - rmax); lsum += ex[j]; }
    red[t] = lsum; __syncthreads();
    for (int s = 64; s > 0; s >>= 1) {
        if (t < s) red[t] += red[t + s];
        __syncthreads();
    }
    float inv = 1.f / red[0]; __syncthreads();

    float amax2 = 2.f * __uint_as_float(g_amax_bits);
    float invA = amax2 > 0.f ? 1.f / amax2 : 0.f;

    float attj[4]; float pm = 0.f;
    #pragma unroll
    for (int j = 0; j < 4; j++) {
        float att = ex[j] * inv;
        attj[j] = att;
        float adjn = (w[j] >= 0) ? (2.f * adj_vals[w[j]]) * invA : 0.f;
        out[r * N_NODES + t + 128 * j] = att * adjn;
        pm += att;
    }
    g_P[r * MG + t] = pm;          // c & 127 == t for all 4 cols

    // one float4 reduction for the 4 column-block sums
    red4[t] = make_float4(attj[0], attj[1], attj[2], attj[3]);
    __syncthreads();
    for (int s = 64; s > 0; s >>= 1) {
        if (t < s) {
            float4 a4 = red4[t], b4 = red4[t + s];
            red4[t] = make_float4(a4.x + b4.x, a4.y + b4.y, a4.z + b4.z, a4.w + b4.w);
        }
        __syncthreads();
    }
    if (t < 4) {
        float4 rr = red4[0];
        float v = (t == 0) ? rr.x : (t == 1) ? rr.y : (t == 2) ? rr.z : rr.w;
        g_P[r * MG + 128 + t] = v;
    }
}

// ---------------- K5: hp = P(512,132) @ G(132,1024) ----------------
__global__ void __launch_bounds__(256) k_hp() {
    __shared__ float Ps[32][MG];
    __shared__ float Gs[MG][32];
    int bx = blockIdx.x;            // col tile (32)
    int by = blockIdx.y;            // row tile (16)
    int tid = threadIdx.x;

    for (int i = tid; i < 32 * MG; i += 256) {
        int rr = i / MG, kk = i % MG;
        Ps[rr][kk] = g_P[(by * 32 + rr) * MG + kk];
    }
    for (int i = tid; i < MG * 32; i += 256) {
        int kk = i / 32, cc = i % 32;
        Gs[kk][cc] = g_G[kk * HID + bx * 32 + cc];
    }
    __syncthreads();

    int tx = tid & 7, ty = tid >> 3;   // ty: row 0..31, tx: col4 0..7
    float4 acc = make_float4(0.f, 0.f, 0.f, 0.f);
    #pragma unroll 4
    for (int k = 0; k < MG; k++) {
        float p = Ps[ty][k];
        float4 gv = *(float4*)&Gs[k][tx * 4];
        acc.x += p * gv.x; acc.y += p * gv.y;
        acc.z += p * gv.z; acc.w += p * gv.w;
    }
    int row = by * 32 + ty, col = bx * 32 + tx * 4;
    *(float4*)&g_hp[row * HID + col] = acc;
}

// ---------------- K6: gemv, RG=2 rows per block, CH=16 chunks (R7) ---------
__global__ void __launch_bounds__(256) k_gemv(const float* __restrict__ lin_w) {
    int chunk = blockIdx.x;          // 0..CH-1
    int rg = blockIdx.y;             // 0..NRG-1
    int t = threadIdx.x;             // 256
    int row0 = rg * RG;
    int r0 = row0 < NOUT ? row0 : NOUT - 1;
    int r1 = row0 + 1 < NOUT ? row0 + 1 : NOUT - 1;

    const float4* w0 = (const float4*)(lin_w + (size_t)r0 * HPLEN + (size_t)chunk * CHLEN);
    const float4* w1 = (const float4*)(lin_w + (size_t)r1 * HPLEN + (size_t)chunk * CHLEN);
    const float4* vp = (const float4*)(g_hp + (size_t)chunk * CHLEN);

    float a0 = 0.f, a1 = 0.f;
    #pragma unroll 8
    for (int i = t; i < CHLEN / 4; i += 256) {
        float4 v = __ldg(&vp[i]);
        float4 x = __ldcs(&w0[i]);
        float4 y = __ldcs(&w1[i]);
        a0 += x.x * v.x + x.y * v.y + x.z * v.z + x.w * v.w;
        a1 += y.x * v.x + y.y * v.y + y.z * v.z + y.w * v.w;
    }

    __shared__ float sh[2][256];
    sh[0][t] = a0; sh[1][t] = a1;
    __syncthreads();
    for (int s = 128; s > 0; s >>= 1) {
        if (t < s) { sh[0][t] += sh[0][t + s]; sh[1][t] += sh[1][t + s]; }
        __syncthreads();
    }
    if (t < RG) {
        int row = row0 + t;
        if (row < NOUT) g_partial[row * CH + chunk] = sh[t][0];
    }
}

// ---------------- K7: finalize + min/max normalize ----------------
__global__ void k_final(const float* __restrict__ lin_b, float* __restrict__ out) {
    __shared__ float vals[NOUT];
    __shared__ float smin[256], smax[256];
    int t = threadIdx.x;            // 256
    for (int i = t; i < NOUT; i += 256) {
        float s = lin_b[i];
        #pragma unroll
        for (int c = 0; c < CH; c++) s += g_partial[i * CH + c];
        vals[i] = s;
    }
    __syncthreads();
    float mn = 1e30f, mx = -1e30f;
    for (int i = t; i < NOUT; i += 256) {
        mn = fminf(mn, vals[i]);
        mx = fmaxf(mx, vals[i]);
    }
    smin[t] = mn; smax[t] = mx; __syncthreads();
    for (int s = 128; s > 0; s >>= 1) {
        if (t < s) {
            smin[t] = fminf(smin[t], smin[t + s]);
            smax[t] = fmaxf(smax[t], smax[t + s]);
        }
        __syncthreads();
    }
    float gmn = smin[0], gmx = smax[0];
    float denom = gmx - gmn;
    for (int i = t; i < NOUT; i += 256)
        out[NN + i] = (denom == 0.f) ? 0.5f : (vals[i] - gmn) / denom;
}

// ---------------- launch (R7 structure) ----------------
extern "C" void kernel_launch(void* const* d_in, const int* in_sizes, int n_in,
                              void* d_out, int out_size) {
    const float* img = (const float*)d_in[0];
    const int*   er  = (const int*)d_in[1];
    const int*   ec  = (const int*)d_in[2];
    const float* av  = (const float*)d_in[3];
    const float* X   = (const float*)d_in[4];
    const float* W   = (const float*)d_in[5];
    const float* a   = (const float*)d_in[6];
    const float* lw  = (const float*)d_in[7];
    const float* lb  = (const float*)d_in[8];
    float* out = (float*)d_out;

    static cudaStream_t s2 = []() {
        cudaStream_t s; cudaStreamCreateWithFlags(&s, cudaStreamNonBlocking); return s;
    }();
    static cudaEvent_t e0 = []() {
        cudaEvent_t e; cudaEventCreateWithFlags(&e, cudaEventDisableTiming); return e;
    }();
    static cudaEvent_t e1 = []() {
        cudaEvent_t e; cudaEventCreateWithFlags(&e, cudaEventDisableTiming); return e;
    }();
    static bool attr_set = []() {
        cudaFuncSetAttribute(k_gemm_bf16, cudaFuncAttributeMaxDynamicSharedMemorySize,
                             GEMM_SMEM_BYTES);
        return true;
    }();
    (void)attr_set;

    void* winner_ptr = nullptr;
    void* amax_ptr = nullptr;
    cudaGetSymbolAddress(&winner_ptr, g_winner);
    cudaGetSymbolAddress(&amax_ptr, g_amax_bits);

    // fork: edge path on s2
    cudaEventRecord(e0, 0);
    cudaStreamWaitEvent(s2, e0, 0);
    cudaMemsetAsync(winner_ptr, 0xFF, NN * sizeof(int), s2);        // winner = -1
    cudaMemsetAsync(amax_ptr, 0x00, sizeof(unsigned int), s2);      // amax = 0
    k_scatter<<<64, 256, 0, s2>>>(er, ec);
    k_amax<<<64, 256, 0, s2>>>(er, ec, av);
    cudaEventRecord(e1, s2);

    // main path on default stream
    int prep_blocks = (NW8 + NA8 + 255) / 256;
    k_prep<<<prep_blocks, 256>>>(W, X, img);
    dim3 g1(8, 3, SPLITK);
    k_gemm_bf16<<<g1, 128, GEMM_SMEM_BYTES>>>();
    k_reduce_gs<<<MG, 256>>>(a);

    // join
    cudaStreamWaitEvent(0, e1, 0);
    k_row<<<512, 128>>>(av, out);
    dim3 g5(32, 16);
    k_hp<<<g5, 256>>>();
    dim3 g6(CH, NRG);
    k_gemv<<<g6, 256>>>(lw);
    k_final<<<1, 256>>>(lb, out);
}